// round 1
// baseline (speedup 1.0000x reference)
#include <cuda_runtime.h>
#include <math.h>

#define FULL 0xffffffffu

constexpr int B = 128, J = 32, I = 1152, N = 16;
constexpr int TI = 32;            // i-values per block tile
constexpr int NCH = I / TI;       // 36 chunks
constexpr int TPB = 256;
constexpr int WARPS = TPB / 32;   // 8
constexpr int ROW = TI * N + 20;  // 532 floats: 532 % 32 == 20 -> 4-phase LDS.128
constexpr int SMEM_FLOATS = J * ROW + 512 + 512 + WARPS;
constexpr int KTH = 8;            // int(0.3*32) - 1 = 9th smallest (index 8)

// Scratch (device globals only — no allocation allowed)
__device__ float g_spart[NCH * B * J * N];  // 9.4 MB partial s sums
__device__ float g_v[2][B * J * N];         // v0, v1
__device__ float g_entp[B * NCH];           // per-block entropy partials
__device__ float g_stat1;

__device__ __forceinline__ float warp_max(float x) {
#pragma unroll
  for (int m = 16; m; m >>= 1) x = fmaxf(x, __shfl_xor_sync(FULL, x, m));
  return x;
}
__device__ __forceinline__ float warp_sum(float x) {
#pragma unroll
  for (int m = 16; m; m >>= 1) x += __shfl_xor_sync(FULL, x, m);
  return x;
}

// Mask bottom-9 along j (lane axis): kth-smallest via warp bitonic sort,
// then x <= kth -> -inf (matches torch/jnp sort-then-mask incl. ties).
__device__ __forceinline__ float sparsify(float x, int lane) {
  float xs = x;
#pragma unroll
  for (int k = 2; k <= 32; k <<= 1) {
#pragma unroll
    for (int j = k >> 1; j > 0; j >>= 1) {
      float y = __shfl_xor_sync(FULL, xs, j);
      bool take_min = (((lane & j) == 0) == ((lane & k) == 0));
      xs = take_min ? fminf(xs, y) : fmaxf(xs, y);
    }
  }
  float kth = __shfl_sync(FULL, xs, KTH);
  return (x <= kth) ? -INFINITY : x;
}

// One fused pass over u_hat.
// ITER 0: c = 1/32 (softmax of zeros), just accumulate s0.
// ITER 1: b1 = sparsify(u.v0); c = softmax(b1); entropy; s1.
// ITER 2: b1 = sparsify(u.v0); b2 = sparsify(b1 + u.v1); c = softmax(b2); entropy; s2.
template <int ITER>
__global__ void __launch_bounds__(TPB) pass_kernel(const float* __restrict__ u) {
  extern __shared__ float smem[];
  float* us = smem;                 // [J][ROW] staged tile
  float* v0s = smem + J * ROW;      // [512]
  float* v1s = v0s + 512;           // [512]
  float* entw = v1s + 512;          // [WARPS]

  const int b = blockIdx.y;
  const int ch = blockIdx.x;
  const int i0 = ch * TI;
  const int tid = threadIdx.x;
  const int w = tid >> 5, lane = tid & 31;

  // Stage u[b, :, i0:i0+TI, :] — fully coalesced float4 streaming.
  const float4* ub = reinterpret_cast<const float4*>(u);
#pragma unroll
  for (int t = 0; t < (J * TI * N / 4) / TPB; ++t) {  // 16 iterations
    int f = tid + t * TPB;
    int j = f >> 7;    // 128 float4 per j-row
    int o = f & 127;
    float4 val = ub[((b * J + j) * I + i0) * (N / 4) + o];
    *reinterpret_cast<float4*>(&us[j * ROW + o * 4]) = val;
  }
  if (ITER >= 1)
    for (int t = tid; t < J * N; t += TPB) v0s[t] = g_v[0][b * J * N + t];
  if (ITER == 2)
    for (int t = tid; t < J * N; t += TPB) v1s[t] = g_v[1][b * J * N + t];
  __syncthreads();

  float v0r[N], v1r[N];
  if (ITER >= 1) {
#pragma unroll
    for (int n = 0; n < N; ++n) v0r[n] = v0s[lane * N + n];
  }
  if (ITER == 2) {
#pragma unroll
    for (int n = 0; n < N; ++n) v1r[n] = v1s[lane * N + n];
  }

  float sacc[N];
#pragma unroll
  for (int n = 0; n < N; ++n) sacc[n] = 0.f;
  float entacc = 0.f;

#pragma unroll
  for (int t = 0; t < TI / WARPS; ++t) {  // 4 i per warp
    const int ii = w + t * WARPS;
    float ur[N];
    const float4* up = reinterpret_cast<const float4*>(&us[lane * ROW + ii * N]);
#pragma unroll
    for (int q = 0; q < 4; ++q) {
      float4 x = up[q];
      ur[q * 4 + 0] = x.x; ur[q * 4 + 1] = x.y;
      ur[q * 4 + 2] = x.z; ur[q * 4 + 3] = x.w;
    }
    float c;
    if (ITER == 0) {
      c = 1.0f / 32.0f;
    } else {
      float d0 = 0.f;
#pragma unroll
      for (int n = 0; n < N; ++n) d0 = fmaf(ur[n], v0r[n], d0);
      float bv = sparsify(d0, lane);
      if (ITER == 2) {
        float d1 = 0.f;
#pragma unroll
        for (int n = 0; n < N; ++n) d1 = fmaf(ur[n], v1r[n], d1);
        bv = sparsify(bv + d1, lane);
      }
      float m = warp_max(bv);
      bool masked = isinf(bv);
      float e = masked ? 0.f : __expf(bv - m);
      float S = warp_sum(e);
      c = e / S;
      float term = masked ? 0.f : c * (bv - m);
      float tsum = warp_sum(term);
      entacc += __logf(S) - tsum;  // -sum(c*log c), masked terms contribute 0
    }
#pragma unroll
    for (int n = 0; n < N; ++n) sacc[n] = fmaf(c, ur[n], sacc[n]);
  }

  if (ITER >= 1 && lane == 0) entw[w] = entacc;
  __syncthreads();  // all warps done reading the tile — safe to reuse `us`

  // Warp partials (lane=j) -> smem (stride 17: conflict-free) -> block reduce.
  float* red = us;
#pragma unroll
  for (int n = 0; n < N; ++n) red[w * 544 + lane * 17 + n] = sacc[n];
  __syncthreads();

  float* outp = &g_spart[(ch * B + b) * (J * N)];
#pragma unroll
  for (int r = 0; r < (J * N) / TPB; ++r) {  // 2
    int e = tid + r * TPB;
    int jj = e >> 4, nn = e & 15;
    float s = 0.f;
#pragma unroll
    for (int ww = 0; ww < WARPS; ++ww) s += red[ww * 544 + jj * 17 + nn];
    outp[e] = s;
  }
  if (ITER >= 1 && tid == 0) {
    float es = 0.f;
#pragma unroll
    for (int ww = 0; ww < WARPS; ++ww) es += entw[ww];
    g_entp[b * NCH + ch] = es;
  }
}

// Reduce chunk partials -> s[b,j,n]; bias + reset + squash -> v.
// ITER 0 -> g_v[0], ITER 1 -> g_v[1] (+ stat1), ITER 2 -> d_out (+ all stats).
// Stats summed in fixed order (deterministic across graph replays).
template <int ITER>
__global__ void __launch_bounds__(TPB) reduce_kernel(const float* __restrict__ bias,
                                                     float* __restrict__ out,
                                                     int has_stats) {
  const int tid = threadIdx.x;
  const int g = blockIdx.x * TPB + tid;  // 0 .. 65535
  const int n = g & 15;
  const int j = (g >> 4) & 31;

  float s = 0.f;
#pragma unroll
  for (int c = 0; c < NCH; ++c) s += g_spart[c * (B * J * N) + g];

  // 16-lane group reductions over n (rows are 16-aligned inside the warp)
  float ssum = s;
#pragma unroll
  for (int m = 8; m; m >>= 1) ssum += __shfl_xor_sync(FULL, ssum, m);
  float sb = (ssum == 0.f) ? 0.f : s + bias[j * N + n];
  float sq = sb * sb;
#pragma unroll
  for (int m = 8; m; m >>= 1) sq += __shfl_xor_sync(FULL, sq, m);
  float v = sb * (sq / (1.f + sq)) * rsqrtf(sq);  // squash

  if (ITER == 0)      g_v[0][g] = v;
  else if (ITER == 1) g_v[1][g] = v;
  else                out[g] = v;

  if (ITER >= 1 && blockIdx.x == 0) {
    __shared__ float es[TPB];
    float acc = 0.f;
    for (int t = tid; t < NCH * B; t += TPB) acc += g_entp[t];
    es[tid] = acc;
    __syncthreads();
    for (int step = TPB / 2; step; step >>= 1) {
      if (tid < step) es[tid] += es[tid + step];
      __syncthreads();
    }
    if (tid == 0) {
      float mean = es[0] / (float)(B * I);
      if (ITER == 1) {
        g_stat1 = mean;
      } else if (has_stats) {
        out[B * J * N + 0] = logf(32.0f);  // softmax of zeros -> entropy = ln(32)
        out[B * J * N + 1] = g_stat1;
        out[B * J * N + 2] = mean;
      }
    }
  }
}

extern "C" void kernel_launch(void* const* d_in, const int* in_sizes, int n_in,
                              void* d_out, int out_size) {
  const float* u = (const float*)d_in[0];
  const float* bias = (const float*)d_in[1];
  float* out = (float*)d_out;
  const int has_stats = (out_size >= B * J * N + 3) ? 1 : 0;

  const size_t sh = SMEM_FLOATS * sizeof(float);  // ~72 KB
  cudaFuncSetAttribute(pass_kernel<0>, cudaFuncAttributeMaxDynamicSharedMemorySize, (int)sh);
  cudaFuncSetAttribute(pass_kernel<1>, cudaFuncAttributeMaxDynamicSharedMemorySize, (int)sh);
  cudaFuncSetAttribute(pass_kernel<2>, cudaFuncAttributeMaxDynamicSharedMemorySize, (int)sh);

  dim3 grid(NCH, B);
  pass_kernel<0><<<grid, TPB, sh>>>(u);
  reduce_kernel<0><<<(B * J * N) / TPB, TPB>>>(bias, out, has_stats);
  pass_kernel<1><<<grid, TPB, sh>>>(u);
  reduce_kernel<1><<<(B * J * N) / TPB, TPB>>>(bias, out, has_stats);
  pass_kernel<2><<<grid, TPB, sh>>>(u);
  reduce_kernel<2><<<(B * J * N) / TPB, TPB>>>(bias, out, has_stats);
}

// round 2
// speedup vs baseline: 1.3377x; 1.3377x over previous
#include <cuda_runtime.h>
#include <math.h>

#define FULL 0xffffffffu

constexpr int B = 128, J = 32, I = 1152, N = 16;
constexpr int TI = 16;              // i per tile
constexpr int ROW = TI * N + 4;     // 260 floats: lane*260 mod 32 = lane*4 -> conflict-free LDS.128
constexpr int NCHB = 2;             // blocks per batch b
constexpr int IPB = I / NCHB;       // 576 i per block
constexpr int TPT = IPB / TI;       // 36 tiles per block
constexpr int TPB = 256, WARPS = 8;
constexpr int KTH = 8;              // int(0.3*32)-1
constexpr int BUF = J * ROW;        // 8320 floats per buffer
constexpr int REDSTRIDE = 544;      // 32*17
constexpr int SMEM_FLOATS = 2 * BUF + 512 + 512 + 8 + WARPS * REDSTRIDE;

__device__ float g_spart[3][NCHB][B][J * N];  // per-pass partial s
__device__ float g_entp[3][B * NCHB];         // per-pass entropy partials

__device__ __forceinline__ float warp_max(float x) {
#pragma unroll
  for (int m = 16; m; m >>= 1) x = fmaxf(x, __shfl_xor_sync(FULL, x, m));
  return x;
}
__device__ __forceinline__ float warp_sum(float x) {
#pragma unroll
  for (int m = 16; m; m >>= 1) x += __shfl_xor_sync(FULL, x, m);
  return x;
}
__device__ __forceinline__ float grp16_sum(float x) {
#pragma unroll
  for (int m = 8; m; m >>= 1) x += __shfl_xor_sync(FULL, x, m);
  return x;
}

// bottom-9 mask along j (lane axis): kth smallest via bitonic sort, x<=kth -> -inf
__device__ __forceinline__ float sparsify(float x, int lane) {
  float xs = x;
#pragma unroll
  for (int k = 2; k <= 32; k <<= 1) {
#pragma unroll
    for (int j = k >> 1; j > 0; j >>= 1) {
      float y = __shfl_xor_sync(FULL, xs, j);
      bool take_min = (((lane & j) == 0) == ((lane & k) == 0));
      xs = take_min ? fminf(xs, y) : fmaxf(xs, y);
    }
  }
  float kth = __shfl_sync(FULL, xs, KTH);
  return (x <= kth) ? -INFINITY : x;
}

// combine two chunk partials -> s; bias + reset + squash -> v (smem)
__device__ __forceinline__ void combine_v(const float* __restrict__ p0,
                                          const float* __restrict__ p1,
                                          const float* __restrict__ bias,
                                          float* vout, int tid) {
#pragma unroll
  for (int r = 0; r < 2; ++r) {
    int e = tid + r * TPB;  // 0..511, e = j*16+n, 16-groups warp-aligned
    float s = p0[e] + p1[e];
    float ssum = grp16_sum(s);
    float sb = (ssum == 0.f) ? 0.f : s + bias[e];
    float sq = grp16_sum(sb * sb);
    vout[e] = (sq > 0.f) ? sb * (sq / (1.f + sq)) * rsqrtf(sq) : 0.f;
  }
}

template <int ITER>
__global__ void __launch_bounds__(TPB) pass_kernel(const float* __restrict__ u,
                                                   const float* __restrict__ bias) {
  extern __shared__ float smem[];
  float* buf0 = smem;
  float* buf1 = smem + BUF;
  float* v0s = smem + 2 * BUF;
  float* v1s = v0s + 512;
  float* entw = v1s + 512;
  float* red = entw + 8;

  const int b = blockIdx.y, g = blockIdx.x;
  const int tid = threadIdx.x, w = tid >> 5, lane = tid & 31;
  const int ibase = g * IPB;

  // issue one 32KB tile via cp.async.cg (L1-bypass streaming)
  auto issue = [&](int t, float* buf) {
#pragma unroll
    for (int k = 0; k < 8; ++k) {
      int f = tid + k * TPB;      // 2048 chunks of 16B
      int j = f >> 6, o = f & 63; // 64 chunks per j-row
      const float* gp = u + (((size_t)b * J + j) * I + (ibase + t * TI)) * N + o * 4;
      unsigned sa = (unsigned)__cvta_generic_to_shared(buf + j * ROW + o * 4);
      asm volatile("cp.async.cg.shared.global [%0], [%1], 16;\n" ::"r"(sa), "l"(gp));
    }
    asm volatile("cp.async.commit_group;\n");
  };

  issue(0, buf0);  // prologue load overlaps with combine below

  if (ITER >= 1) combine_v(g_spart[0][0][b], g_spart[0][1][b], bias, v0s, tid);
  if (ITER == 2) combine_v(g_spart[1][0][b], g_spart[1][1][b], bias, v1s, tid);
  __syncthreads();

  float v0r[N], v1r[N];
  if (ITER >= 1) {
#pragma unroll
    for (int n = 0; n < N; ++n) v0r[n] = v0s[lane * N + n];
  }
  if (ITER == 2) {
#pragma unroll
    for (int n = 0; n < N; ++n) v1r[n] = v1s[lane * N + n];
  }

  float sacc[N];
#pragma unroll
  for (int n = 0; n < N; ++n) sacc[n] = 0.f;
  float entacc = 0.f;

  for (int t = 0; t < TPT; ++t) {
    if (t + 1 < TPT) {
      issue(t + 1, ((t + 1) & 1) ? buf1 : buf0);
      asm volatile("cp.async.wait_group 1;\n" ::: "memory");
    } else {
      asm volatile("cp.async.wait_group 0;\n" ::: "memory");
    }
    __syncthreads();
    const float* us = (t & 1) ? buf1 : buf0;

#pragma unroll
    for (int q = 0; q < TI / WARPS; ++q) {  // 2 i per warp
      const int ii = w + q * WARPS;
      float ur[N];
      const float4* up = reinterpret_cast<const float4*>(&us[lane * ROW + ii * N]);
#pragma unroll
      for (int p = 0; p < 4; ++p) {
        float4 x = up[p];
        ur[p * 4 + 0] = x.x; ur[p * 4 + 1] = x.y;
        ur[p * 4 + 2] = x.z; ur[p * 4 + 3] = x.w;
      }
      float c;
      if (ITER == 0) {
        c = 1.0f / 32.0f;  // softmax of zeros
      } else {
        float d0 = 0.f;
#pragma unroll
        for (int n = 0; n < N; ++n) d0 = fmaf(ur[n], v0r[n], d0);
        float bv = sparsify(d0, lane);
        if (ITER == 2) {
          float d1 = 0.f;
#pragma unroll
          for (int n = 0; n < N; ++n) d1 = fmaf(ur[n], v1r[n], d1);
          bv = sparsify(bv + d1, lane);
        }
        float m = warp_max(bv);
        bool masked = isinf(bv);
        float e = masked ? 0.f : __expf(bv - m);
        float S = warp_sum(e);
        c = e / S;
        float term = masked ? 0.f : c * (bv - m);
        entacc += __logf(S) - warp_sum(term);  // -sum(c log c)
      }
#pragma unroll
      for (int n = 0; n < N; ++n) sacc[n] = fmaf(c, ur[n], sacc[n]);
    }
    __syncthreads();  // all readers done before buffer reuse
  }

  if (ITER >= 1 && lane == 0) entw[w] = entacc;
  __syncthreads();
#pragma unroll
  for (int n = 0; n < N; ++n) red[w * REDSTRIDE + lane * 17 + n] = sacc[n];
  __syncthreads();

  float* outp = g_spart[ITER][g][b];
#pragma unroll
  for (int r = 0; r < 2; ++r) {
    int e = tid + r * TPB;
    int jj = e >> 4, nn = e & 15;
    float s = 0.f;
#pragma unroll
    for (int ww = 0; ww < WARPS; ++ww) s += red[ww * REDSTRIDE + jj * 17 + nn];
    outp[e] = s;
  }
  if (ITER >= 1 && tid == 0) {
    float es = 0.f;
#pragma unroll
    for (int ww = 0; ww < WARPS; ++ww) es += entw[ww];
    g_entp[ITER][b * NCHB + g] = es;
  }
}

// last combine + squash -> out, plus the 3 entropy stats (fixed-order: deterministic)
__global__ void __launch_bounds__(TPB) final_kernel(const float* __restrict__ bias,
                                                    float* __restrict__ out,
                                                    int has_stats) {
  const int tid = threadIdx.x;
  const int idx = blockIdx.x * TPB + tid;  // 0..65535
  const int b = idx >> 9, e = idx & 511;

  float s = g_spart[2][0][b][e] + g_spart[2][1][b][e];
  float ssum = grp16_sum(s);
  float sb = (ssum == 0.f) ? 0.f : s + bias[e];
  float sq = grp16_sum(sb * sb);
  out[idx] = (sq > 0.f) ? sb * (sq / (1.f + sq)) * rsqrtf(sq) : 0.f;

  if (has_stats && blockIdx.x == 0) {
    __shared__ float e1[TPB], e2[TPB];
    e1[tid] = g_entp[1][tid];
    e2[tid] = g_entp[2][tid];
    __syncthreads();
    for (int step = TPB / 2; step; step >>= 1) {
      if (tid < step) { e1[tid] += e1[tid + step]; e2[tid] += e2[tid + step]; }
      __syncthreads();
    }
    if (tid == 0) {
      out[B * J * N + 0] = logf(32.0f);
      out[B * J * N + 1] = e1[0] / (float)(B * I);
      out[B * J * N + 2] = e2[0] / (float)(B * I);
    }
  }
}

extern "C" void kernel_launch(void* const* d_in, const int* in_sizes, int n_in,
                              void* d_out, int out_size) {
  const float* u = (const float*)d_in[0];
  const float* bias = (const float*)d_in[1];
  float* out = (float*)d_out;
  const int has_stats = (out_size >= B * J * N + 3) ? 1 : 0;

  const size_t sh = SMEM_FLOATS * sizeof(float);  // ~88 KB
  cudaFuncSetAttribute(pass_kernel<0>, cudaFuncAttributeMaxDynamicSharedMemorySize, (int)sh);
  cudaFuncSetAttribute(pass_kernel<1>, cudaFuncAttributeMaxDynamicSharedMemorySize, (int)sh);
  cudaFuncSetAttribute(pass_kernel<2>, cudaFuncAttributeMaxDynamicSharedMemorySize, (int)sh);

  dim3 grid(NCHB, B);
  pass_kernel<0><<<grid, TPB, sh>>>(u, bias);
  pass_kernel<1><<<grid, TPB, sh>>>(u, bias);
  pass_kernel<2><<<grid, TPB, sh>>>(u, bias);
  final_kernel<<<(B * J * N) / TPB, TPB>>>(bias, out, has_stats);
}

// round 4
// speedup vs baseline: 1.6513x; 1.2344x over previous
#include <cuda_runtime.h>
#include <math.h>

#define FULL 0xffffffffu

constexpr int B = 128, J = 32, I = 1152, N = 16;
constexpr int TI = 16;              // i per tile
constexpr int ROW = TI * N + 4;     // 260: lane*260 mod 32 = lane*4 -> conflict-free LDS.128
constexpr int NCHB = 2;             // blocks per batch
constexpr int IPB = I / NCHB;       // 576
constexpr int TPT = IPB / TI;       // 36 tiles
constexpr int TPB = 256, WARPS = 8;
constexpr int KTH = 8;              // int(0.3*32)-1
constexpr int BUF = J * ROW;        // 8320 floats
constexpr int BB = TI * J + 8;      // 520 floats (b1 tile)
constexpr int REDSTRIDE = 544;
constexpr int SMEM_FLOATS = 2 * BUF + 2 * BB + 512 + 8 + WARPS * REDSTRIDE;

__device__ float g_spart[3][NCHB][B][J * N];
__device__ float g_entp[2][B * NCHB];      // pass1, pass2 entropy partials
__device__ float g_b1[(size_t)B * I * J];  // 18.9 MB masked logits from pass 1

__device__ __forceinline__ float warp_sum(float x) {
#pragma unroll
  for (int m = 16; m; m >>= 1) x += __shfl_xor_sync(FULL, x, m);
  return x;
}
__device__ __forceinline__ float warp_max(float x) {
#pragma unroll
  for (int m = 16; m; m >>= 1) x = fmaxf(x, __shfl_xor_sync(FULL, x, m));
  return x;
}
__device__ __forceinline__ float grp16_sum(float x) {
#pragma unroll
  for (int m = 8; m; m >>= 1) x += __shfl_xor_sync(FULL, x, m);
  return x;
}

// combine two chunk partials -> s; bias + reset + squash -> v (smem)
__device__ __forceinline__ void combine_v(const float* __restrict__ p0,
                                          const float* __restrict__ p1,
                                          const float* __restrict__ bias,
                                          float* vout, int tid) {
#pragma unroll
  for (int r = 0; r < 2; ++r) {
    int e = tid + r * TPB;  // e = j*16+n, 16-groups warp-aligned
    float s = p0[e] + p1[e];
    float ssum = grp16_sum(s);
    float sb = (ssum == 0.f) ? 0.f : s + bias[e];
    float sq = grp16_sum(sb * sb);
    vout[e] = (sq > 0.f) ? sb * (sq / (1.f + sq)) * rsqrtf(sq) : 0.f;
  }
}

template <int ITER>
__global__ void __launch_bounds__(TPB) pass_kernel(const float* __restrict__ u,
                                                   const float* __restrict__ bias) {
  extern __shared__ float smem[];
  float* buf0 = smem;
  float* buf1 = smem + BUF;
  float* bb0 = smem + 2 * BUF;
  float* bb1 = bb0 + BB;
  float* vs = bb1 + BB;     // 512
  float* entw = vs + 512;   // 8
  float* red = entw + 8;

  const int b = blockIdx.y, g = blockIdx.x;
  const int tid = threadIdx.x, w = tid >> 5, lane = tid & 31;
  const int ibase = g * IPB;
  const float NEG_INF = __int_as_float(0xff800000);

  // serpentine: pass1 walks tiles in reverse so it hits what pass0 left in L2
  auto phys = [&](int t) { return (ITER == 1) ? (TPT - 1 - t) : t; };

  auto issue = [&](int pt, int sel) {
    float* buf = sel ? buf1 : buf0;
#pragma unroll
    for (int k = 0; k < 8; ++k) {
      int f = tid + k * TPB;       // 2048 x 16B
      int j = f >> 6, o = f & 63;  // 64 float4 per j-row
      const float* gp = u + (((size_t)b * J + j) * I + (ibase + pt * TI)) * N + o * 4;
      unsigned sa = (unsigned)__cvta_generic_to_shared(buf + j * ROW + o * 4);
      asm volatile("cp.async.cg.shared.global [%0], [%1], 16;\n" ::"r"(sa), "l"(gp));
    }
    if (ITER == 2 && tid < 128) {  // 2KB b1 tile, contiguous
      float* bb = sel ? bb1 : bb0;
      const float* gp = g_b1 + ((size_t)b * I + ibase + pt * TI) * J + tid * 4;
      unsigned sa = (unsigned)__cvta_generic_to_shared(bb + tid * 4);
      asm volatile("cp.async.cg.shared.global [%0], [%1], 16;\n" ::"r"(sa), "l"(gp));
    }
    asm volatile("cp.async.commit_group;\n");
  };

  issue(phys(0), 0);  // overlaps with prologue combine

  if (ITER == 1) combine_v(g_spart[0][0][b], g_spart[0][1][b], bias, vs, tid);
  if (ITER == 2) combine_v(g_spart[1][0][b], g_spart[1][1][b], bias, vs, tid);
  __syncthreads();

  float vr[N];
  if (ITER >= 1) {
#pragma unroll
    for (int n = 0; n < N; ++n) vr[n] = vs[lane * N + n];
  }

  float sacc[N];
#pragma unroll
  for (int n = 0; n < N; ++n) sacc[n] = 0.f;
  float entacc = 0.f;

  for (int t = 0; t < TPT; ++t) {
    const int pt = phys(t);
    if (t + 1 < TPT) {
      issue(phys(t + 1), (t + 1) & 1);
      asm volatile("cp.async.wait_group 1;\n" ::: "memory");
    } else {
      asm volatile("cp.async.wait_group 0;\n" ::: "memory");
    }
    __syncthreads();
    const float* us = (t & 1) ? buf1 : buf0;
    const float* bb = (t & 1) ? bb1 : bb0;

#pragma unroll
    for (int q = 0; q < TI / WARPS; ++q) {  // 2 i per warp
      const int ii = w + q * WARPS;
      float ur[N];
      const float4* up = reinterpret_cast<const float4*>(&us[lane * ROW + ii * N]);
#pragma unroll
      for (int p = 0; p < 4; ++p) {
        float4 x = up[p];
        ur[p * 4 + 0] = x.x; ur[p * 4 + 1] = x.y;
        ur[p * 4 + 2] = x.z; ur[p * 4 + 3] = x.w;
      }

      if (ITER == 0) {  // c = 1/32 (softmax of zeros); scale applied at writeback
#pragma unroll
        for (int n = 0; n < N; ++n) sacc[n] += ur[n];
        continue;
      }

      float cc;
      if (ITER == 1) {
        float d0 = 0.f;
#pragma unroll
        for (int n = 0; n < N; ++n) d0 = fmaf(ur[n], vr[n], d0);
        // bitonic sort over lanes -> kth smallest + max
        float xs = d0;
#pragma unroll
        for (int k = 2; k <= 32; k <<= 1) {
#pragma unroll
          for (int j = k >> 1; j > 0; j >>= 1) {
            float y = __shfl_xor_sync(FULL, xs, j);
            bool take_min = (((lane & j) == 0) == ((lane & k) == 0));
            xs = take_min ? fminf(xs, y) : fmaxf(xs, y);
          }
        }
        float kth = __shfl_sync(FULL, xs, KTH);
        float m = __shfl_sync(FULL, xs, 31);  // max survives masking
        bool msk = (d0 <= kth);
        float bv = msk ? NEG_INF : d0;
        g_b1[((size_t)b * I + ibase + pt * TI + ii) * J + lane] = bv;
        float e = __expf(bv - m);  // exp(-inf) = 0
        float S = warp_sum(e);
        float T = warp_sum(msk ? 0.f : e * (bv - m));
        entacc += __logf(S) - T / S;
        cc = e / S;
      } else {  // ITER == 2: second sparsify is a no-op (kth of column with 9 -infs = -inf)
        float bv = bb[ii * J + lane];
        float d1 = 0.f;
#pragma unroll
        for (int n = 0; n < N; ++n) d1 = fmaf(ur[n], vr[n], d1);
        float b2 = bv + d1;  // -inf propagates
        bool msk = isinf(b2);
        float m = warp_max(b2);
        float e = __expf(b2 - m);
        float S = warp_sum(e);
        float T = warp_sum(msk ? 0.f : e * (b2 - m));
        entacc += __logf(S) - T / S;
        cc = e / S;
      }
#pragma unroll
      for (int n = 0; n < N; ++n) sacc[n] = fmaf(cc, ur[n], sacc[n]);
    }
    __syncthreads();  // readers done before buffer reuse
  }

  if (ITER >= 1 && lane == 0) entw[w] = entacc;
  __syncthreads();
#pragma unroll
  for (int n = 0; n < N; ++n) red[w * REDSTRIDE + lane * 17 + n] = sacc[n];
  __syncthreads();

  float* outp = g_spart[ITER][g][b];
  const float scale = (ITER == 0) ? (1.0f / 32.0f) : 1.0f;
#pragma unroll
  for (int r = 0; r < 2; ++r) {
    int e = tid + r * TPB;
    int jj = e >> 4, nn = e & 15;
    float s = 0.f;
#pragma unroll
    for (int ww = 0; ww < WARPS; ++ww) s += red[ww * REDSTRIDE + jj * 17 + nn];
    outp[e] = s * scale;
  }
  if (ITER >= 1 && tid == 0) {
    float es = 0.f;
#pragma unroll
    for (int ww = 0; ww < WARPS; ++ww) es += entw[ww];
    g_entp[ITER - 1][b * NCHB + g] = es;
  }
}

__global__ void __launch_bounds__(TPB) final_kernel(const float* __restrict__ bias,
                                                    float* __restrict__ out,
                                                    int has_stats) {
  const int tid = threadIdx.x;
  const int idx = blockIdx.x * TPB + tid;
  const int b = idx >> 9, e = idx & 511;

  float s = g_spart[2][0][b][e] + g_spart[2][1][b][e];
  float ssum = grp16_sum(s);
  float sb = (ssum == 0.f) ? 0.f : s + bias[e];
  float sq = grp16_sum(sb * sb);
  out[idx] = (sq > 0.f) ? sb * (sq / (1.f + sq)) * rsqrtf(sq) : 0.f;

  if (has_stats && blockIdx.x == 0) {
    __shared__ float e1[TPB], e2[TPB];
    e1[tid] = g_entp[0][tid];
    e2[tid] = g_entp[1][tid];
    __syncthreads();
    for (int step = TPB / 2; step; step >>= 1) {
      if (tid < step) { e1[tid] += e1[tid + step]; e2[tid] += e2[tid + step]; }
      __syncthreads();
    }
    if (tid == 0) {
      out[B * J * N + 0] = logf(32.0f);  // entropy of uniform softmax
      out[B * J * N + 1] = e1[0] / (float)(B * I);
      out[B * J * N + 2] = e2[0] / (float)(B * I);
    }
  }
}

extern "C" void kernel_launch(void* const* d_in, const int* in_sizes, int n_in,
                              void* d_out, int out_size) {
  const float* u = (const float*)d_in[0];
  const float* bias = (const float*)d_in[1];
  float* out = (float*)d_out;
  const int has_stats = (out_size >= B * J * N + 3) ? 1 : 0;

  const size_t sh = SMEM_FLOATS * sizeof(float);  // ~90 KB -> 2 blocks/SM
  cudaFuncSetAttribute(pass_kernel<0>, cudaFuncAttributeMaxDynamicSharedMemorySize, (int)sh);
  cudaFuncSetAttribute(pass_kernel<1>, cudaFuncAttributeMaxDynamicSharedMemorySize, (int)sh);
  cudaFuncSetAttribute(pass_kernel<2>, cudaFuncAttributeMaxDynamicSharedMemorySize, (int)sh);

  dim3 grid(NCHB, B);
  pass_kernel<0><<<grid, TPB, sh>>>(u, bias);
  pass_kernel<1><<<grid, TPB, sh>>>(u, bias);
  pass_kernel<2><<<grid, TPB, sh>>>(u, bias);
  final_kernel<<<(B * J * N) / TPB, TPB>>>(bias, out, has_stats);
}